// round 4
// baseline (speedup 1.0000x reference)
#include <cuda_runtime.h>
#include <cstdint>

// Problem constants
#define BB 4
#define SS 2048
#define DD 1024
#define HH 16
#define HSZ 64
#define BHH (BB*HH)       // 64
#define MROWS (BB*SS)     // 8192

// ---------------- scratch (static device globals; no allocation) -------------
__device__ float g_Qh[(size_t)BHH * SS * HSZ];   // [b,h,s,hs]
__device__ float g_Kh[(size_t)BHH * SS * HSZ];
__device__ float g_Vh[(size_t)BHH * SS * HSZ];
__device__ float g_ctx[(size_t)MROWS * DD];      // [b,s,d]

// =============================================================================
// SGEMM: C = A[M,K] * W[N,K]^T   (both K-major), M=8192, N=K=1024
// 128x128 block tile, BK=16, 256 threads, 8x8 per-thread microtile.
// HEAD_OUT: scatter C[m,n] into [b,h,s,hs] layout. Else: C[m*N+n] (+bias).
// =============================================================================
template<bool HEAD_OUT>
__global__ __launch_bounds__(256, 2)
void sgemm_xwT(const float* __restrict__ A, const float* __restrict__ W,
               const float* __restrict__ bias, float* __restrict__ C)
{
    __shared__ float As[16][128];
    __shared__ float Ws[16][128];

    const int tid = threadIdx.x;
    const int ty  = tid >> 4;          // 0..15 -> rows ty*8
    const int tx  = tid & 15;          // 0..15 -> cols tx*8
    const int rowBase = blockIdx.y * 128;
    const int colBase = blockIdx.x * 128;

    const int lr = tid >> 1;           // 0..127 load row
    const int lk = (tid & 1) * 8;      // 0 or 8 k-offset

    const float* Aload = A + (size_t)(rowBase + lr) * DD + lk;
    const float* Wload = W + (size_t)(colBase + lr) * DD + lk;

    float acc[8][8];
#pragma unroll
    for (int r = 0; r < 8; r++)
#pragma unroll
        for (int c = 0; c < 8; c++) acc[r][c] = 0.f;

    for (int kt = 0; kt < DD; kt += 16) {
        float4 a0 = *(const float4*)(Aload + kt);
        float4 a1 = *(const float4*)(Aload + kt + 4);
        float4 w0 = *(const float4*)(Wload + kt);
        float4 w1 = *(const float4*)(Wload + kt + 4);

        __syncthreads();   // previous iteration's smem reads complete
        As[lk + 0][lr] = a0.x; As[lk + 1][lr] = a0.y;
        As[lk + 2][lr] = a0.z; As[lk + 3][lr] = a0.w;
        As[lk + 4][lr] = a1.x; As[lk + 5][lr] = a1.y;
        As[lk + 6][lr] = a1.z; As[lk + 7][lr] = a1.w;
        Ws[lk + 0][lr] = w0.x; Ws[lk + 1][lr] = w0.y;
        Ws[lk + 2][lr] = w0.z; Ws[lk + 3][lr] = w0.w;
        Ws[lk + 4][lr] = w1.x; Ws[lk + 5][lr] = w1.y;
        Ws[lk + 6][lr] = w1.z; Ws[lk + 7][lr] = w1.w;
        __syncthreads();

#pragma unroll
        for (int kk = 0; kk < 16; kk++) {
            float a[8], w[8];
            float4 t;
            t = *(const float4*)&As[kk][ty * 8];     a[0]=t.x; a[1]=t.y; a[2]=t.z; a[3]=t.w;
            t = *(const float4*)&As[kk][ty * 8 + 4]; a[4]=t.x; a[5]=t.y; a[6]=t.z; a[7]=t.w;
            t = *(const float4*)&Ws[kk][tx * 8];     w[0]=t.x; w[1]=t.y; w[2]=t.z; w[3]=t.w;
            t = *(const float4*)&Ws[kk][tx * 8 + 4]; w[4]=t.x; w[5]=t.y; w[6]=t.z; w[7]=t.w;
#pragma unroll
            for (int r = 0; r < 8; r++)
#pragma unroll
                for (int c = 0; c < 8; c++)
                    acc[r][c] = fmaf(a[r], w[c], acc[r][c]);
        }
    }

    // ------------------------- epilogue -------------------------
#pragma unroll
    for (int r = 0; r < 8; r++) {
        const int m = rowBase + ty * 8 + r;
        if (HEAD_OUT) {
            const int b = m >> 11;            // m / SS
            const int s = m & (SS - 1);
#pragma unroll
            for (int cg = 0; cg < 8; cg += 4) {
                const int n  = colBase + tx * 8 + cg;
                const int h  = n >> 6;
                const int hs = n & 63;
                float4 v;
                v.x = acc[r][cg + 0]; v.y = acc[r][cg + 1];
                v.z = acc[r][cg + 2]; v.w = acc[r][cg + 3];
                *(float4*)&C[(((size_t)(b * HH + h)) * SS + s) * HSZ + hs] = v;
            }
        } else {
#pragma unroll
            for (int cg = 0; cg < 8; cg += 4) {
                const int n = colBase + tx * 8 + cg;
                float4 bv = *(const float4*)&bias[n];
                float4 v;
                v.x = acc[r][cg + 0] + bv.x; v.y = acc[r][cg + 1] + bv.y;
                v.z = acc[r][cg + 2] + bv.z; v.w = acc[r][cg + 3] + bv.w;
                *(float4*)&C[(size_t)m * DD + n] = v;
            }
        }
    }
}

// =============================================================================
// Causal flash attention, fp32.
// Grid: (S/64 query tiles, B*H). 256 threads = 16x16, 4x4 microtile.
// Online softmax in registers (row state replicated across tx lanes via shfl).
// Writes O directly into [b,s,d] context layout.
// =============================================================================
#define FLD 68   // padded leading dim (float4-aligned)

__global__ __launch_bounds__(256, 2)
void flash_kernel(const float* __restrict__ Q, const float* __restrict__ K,
                  const float* __restrict__ V, float* __restrict__ ctx)
{
    extern __shared__ float sm[];
    float* Qs = sm;                 // [hs][i]  (transposed)
    float* Ks = sm + 64 * FLD;      // [hs][j]  (transposed)
    float* Vs = sm + 2 * 64 * FLD;  // [j][d]   (natural)
    float* Ps = sm + 3 * 64 * FLD;  // [j][i]   (transposed)

    const int tid = threadIdx.x;
    const int ty  = tid >> 4;              // query rows i0 = ty*4
    const int tx  = tid & 15;              // key cols / out dims j0 = tx*4
    const int i0  = ty * 4;
    const int j0  = tx * 4;
    const int qt  = blockIdx.x;
    const int bh  = blockIdx.y;

    // load Q tile transposed: Qs[c][r] = Q[qg=qt*64+r][c]
    const float* Qbase = Q + ((size_t)bh * SS + qt * 64) * HSZ;
    for (int idx = tid; idx < 64 * 64; idx += 256) {
        const int r = idx >> 6, c = idx & 63;
        Qs[c * FLD + r] = Qbase[r * HSZ + c];
    }

    float acc[4][4];
    float mrow[4], lrow[4];
#pragma unroll
    for (int r = 0; r < 4; r++) {
        mrow[r] = -1e30f; lrow[r] = 0.f;
#pragma unroll
        for (int c = 0; c < 4; c++) acc[r][c] = 0.f;
    }

    for (int kt = 0; kt <= qt; kt++) {
        const float* Kb = K + ((size_t)bh * SS + kt * 64) * HSZ;
        const float* Vb = V + ((size_t)bh * SS + kt * 64) * HSZ;

        __syncthreads();   // prior GEMM2 reads of Ks/Vs/Ps done; Qs writes (iter 0)
        for (int idx = tid; idx < 64 * 64; idx += 256) {
            const int r = idx >> 6, c = idx & 63;
            Ks[c * FLD + r] = Kb[r * HSZ + c];
            Vs[r * FLD + c] = Vb[r * HSZ + c];
        }
        __syncthreads();

        // ---- GEMM1: s = (Q * K^T) * scale, causal mask ----
        float s[4][4];
#pragma unroll
        for (int r = 0; r < 4; r++)
#pragma unroll
            for (int c = 0; c < 4; c++) s[r][c] = 0.f;

#pragma unroll
        for (int k = 0; k < 64; k++) {
            float4 qv = *(const float4*)&Qs[k * FLD + i0];
            float4 kv = *(const float4*)&Ks[k * FLD + j0];
            float qa[4] = {qv.x, qv.y, qv.z, qv.w};
            float ka[4] = {kv.x, kv.y, kv.z, kv.w};
#pragma unroll
            for (int r = 0; r < 4; r++)
#pragma unroll
                for (int c = 0; c < 4; c++)
                    s[r][c] = fmaf(qa[r], ka[c], s[r][c]);
        }

        const int qg0 = qt * 64 + i0;
        const int kg0 = kt * 64 + j0;
#pragma unroll
        for (int r = 0; r < 4; r++)
#pragma unroll
            for (int c = 0; c < 4; c++) {
                float v = s[r][c] * 0.125f;            // 1/sqrt(64)
                if (kg0 + c > qg0 + r) v = -1e30f;     // causal
                s[r][c] = v;
            }

        // ---- online softmax (row state replicated across tx lanes) ----
#pragma unroll
        for (int r = 0; r < 4; r++) {
            float rm = fmaxf(fmaxf(s[r][0], s[r][1]), fmaxf(s[r][2], s[r][3]));
#pragma unroll
            for (int d = 1; d < 16; d <<= 1)
                rm = fmaxf(rm, __shfl_xor_sync(0xffffffffu, rm, d));
            const float mnew = fmaxf(mrow[r], rm);
            const float corr = __expf(mrow[r] - mnew);
            mrow[r] = mnew;
            float rs = 0.f;
#pragma unroll
            for (int c = 0; c < 4; c++) {
                const float p = __expf(s[r][c] - mnew);
                s[r][c] = p;
                rs += p;
            }
#pragma unroll
            for (int d = 1; d < 16; d <<= 1)
                rs += __shfl_xor_sync(0xffffffffu, rs, d);
            lrow[r] = lrow[r] * corr + rs;
#pragma unroll
            for (int c = 0; c < 4; c++) acc[r][c] *= corr;
        }

        // write P transposed [j][i]
#pragma unroll
        for (int c = 0; c < 4; c++) {
            float4 pv;
            pv.x = s[0][c]; pv.y = s[1][c]; pv.z = s[2][c]; pv.w = s[3][c];
            *(float4*)&Ps[(j0 + c) * FLD + i0] = pv;
        }
        __syncthreads();

        // ---- GEMM2: O += P * V ----
#pragma unroll
        for (int j = 0; j < 64; j++) {
            float4 pv = *(const float4*)&Ps[j * FLD + i0];  // P[i0..i0+3][j]
            float4 vv = *(const float4*)&Vs[j * FLD + j0];  // V[j][d0..d0+3]
            float pa[4] = {pv.x, pv.y, pv.z, pv.w};
            float va[4] = {vv.x, vv.y, vv.z, vv.w};
#pragma unroll
            for (int r = 0; r < 4; r++)
#pragma unroll
                for (int c = 0; c < 4; c++)
                    acc[r][c] = fmaf(pa[r], va[c], acc[r][c]);
        }
    }

    // ---- epilogue: normalize, write to [b,s,d] ----
    const int b = bh >> 4, h = bh & 15;
#pragma unroll
    for (int r = 0; r < 4; r++) {
        const int qg = qt * 64 + i0 + r;
        const float inv = 1.f / lrow[r];
        float4 o;
        o.x = acc[r][0] * inv; o.y = acc[r][1] * inv;
        o.z = acc[r][2] * inv; o.w = acc[r][3] * inv;
        *(float4*)&ctx[((size_t)(b * SS + qg)) * DD + h * HSZ + j0] = o;
    }
}

// =============================================================================
// launch
// =============================================================================
extern "C" void kernel_launch(void* const* d_in, const int* in_sizes, int n_in,
                              void* d_out, int out_size)
{
    const float* x  = (const float*)d_in[0];
    const float* Wk = (const float*)d_in[1];
    const float* Wq = (const float*)d_in[2];
    const float* Wv = (const float*)d_in[3];
    const float* Wo = (const float*)d_in[4];
    const float* bo = (const float*)d_in[5];
    float* out = (float*)d_out;

    float *Qh, *Kh, *Vh, *ctx;
    cudaGetSymbolAddress((void**)&Qh,  g_Qh);
    cudaGetSymbolAddress((void**)&Kh,  g_Kh);
    cudaGetSymbolAddress((void**)&Vh,  g_Vh);
    cudaGetSymbolAddress((void**)&ctx, g_ctx);

    const dim3 gGemm(DD / 128, MROWS / 128);   // (8, 64)
    sgemm_xwT<true><<<gGemm, 256>>>(x, Wq, nullptr, Qh);
    sgemm_xwT<true><<<gGemm, 256>>>(x, Wk, nullptr, Kh);
    sgemm_xwT<true><<<gGemm, 256>>>(x, Wv, nullptr, Vh);

    const int smem = 4 * 64 * FLD * sizeof(float);   // 69632 B
    static bool attr_set = false;
    if (!attr_set) {
        cudaFuncSetAttribute(flash_kernel,
                             cudaFuncAttributeMaxDynamicSharedMemorySize, smem);
        attr_set = true;
    }
    const dim3 gFlash(SS / 64, BHH);           // (32, 64)
    flash_kernel<<<gFlash, 256, smem>>>(Qh, Kh, Vh, ctx);

    sgemm_xwT<false><<<gGemm, 256>>>(ctx, Wo, bo, out);
}